// round 2
// baseline (speedup 1.0000x reference)
#include <cuda_runtime.h>

typedef unsigned long long ull;

// ---------------- shared-memory weight image layout (floats) ----------------
// NH row (76 floats, = 38 f32x2 pairs, matches vector v[38]):
//   [0..31]  W_hh[j][0..31]      (pairs 0..15  <-> v[0..15]  = h)
//   [32..33] (b_ih[j]+b_hh[j],0) (pair  16     <-> v[16]     = (1,0))
//   [34..65] W_ih[j][0..31]      (pairs 17..32 <-> v[17..32] = s)
//   [66..73] W_ih[j][32..39]     (pairs 33..36 <-> v[33..36] = a)
//   [74..75] 0                   (pair  37     <-> v[37]     = (0,0))
// M row (36 floats = 9 ull2): [0..31]=w, [32..33]=(b,0), [34..35]=0
//   consumed against v[0..17] (FC1: h + ONE + harmless 0-weight pad)
//   or u[0..17] (MEAN/STD: hid + ONE + 0)
// Rows j>=16 are skewed +4 floats (16B) so the two distinct addresses per
// warp (rows j and j+16) land 4 banks apart -> conflict-free LDS.128.
#define NH_STRIDE 76
#define M_STRIDE  36
#define FC1_OFF   (32*NH_STRIDE + 4)              // 2436
#define MEAN_OFF  (FC1_OFF + 32*M_STRIDE + 4)     // 3592
#define STD_OFF   (MEAN_OFF + 32*M_STRIDE + 4)    // 4748
#define SMEM_FLOATS (STD_OFF + 32*M_STRIDE + 4)   // 5904 floats = 23616 B

union F4U { float4 f; ulonglong2 u; };

__device__ __forceinline__ ull pack2(float lo, float hi){
  ull r; asm("mov.b64 %0, {%1,%2};" : "=l"(r) : "f"(lo), "f"(hi)); return r;
}
__device__ __forceinline__ float2 unpack2(ull v){
  float2 r; asm("mov.b64 {%0,%1}, %2;" : "=f"(r.x), "=f"(r.y) : "l"(v)); return r;
}
// packed fp32x2 FMA (Blackwell): 2 fp32 FMAs per issue slot
__device__ __forceinline__ ull fma2(ull a, ull b, ull c){
  ull d; asm("fma.rn.f32x2 %0, %1, %2, %3;" : "=l"(d) : "l"(a), "l"(b), "l"(c)); return d;
}
__device__ __forceinline__ float hsum(ull a){ float2 f = unpack2(a); return f.x + f.y; }

__device__ __forceinline__ float tanh_fast(float x){
  float e = __expf(2.0f * x);                 // x>>0 -> inf -> 1-0 = 1; x<<0 -> 0 -> -1
  return 1.0f - __fdividef(2.0f, e + 1.0f);
}
__device__ __forceinline__ float softplus_fast(float x){
  float e = __expf(-fabsf(x));
  return fmaxf(x, 0.0f) + __logf(1.0f + e);
}

// 4 simultaneous row-dot-products against packed vector v (NP ull2 per row)
template<int NP>
__device__ __forceinline__ void dot4(const float* r0, const float* r1,
                                     const float* r2, const float* r3,
                                     const ull* v, float* o){
  const ulonglong2* p0 = (const ulonglong2*)r0;
  const ulonglong2* p1 = (const ulonglong2*)r1;
  const ulonglong2* p2 = (const ulonglong2*)r2;
  const ulonglong2* p3 = (const ulonglong2*)r3;
  ull a0=0ull, a1=0ull, a2=0ull, a3=0ull;
#pragma unroll
  for (int p=0;p<NP;p++){
    ulonglong2 w0=p0[p], w1=p1[p], w2=p2[p], w3=p3[p];
    ull vl=v[2*p], vh=v[2*p+1];
    a0=fma2(w0.x,vl,a0); a0=fma2(w0.y,vh,a0);
    a1=fma2(w1.x,vl,a1); a1=fma2(w1.y,vh,a1);
    a2=fma2(w2.x,vl,a2); a2=fma2(w2.y,vh,a2);
    a3=fma2(w3.x,vl,a3); a3=fma2(w3.y,vh,a3);
  }
  o[0]=hsum(a0); o[1]=hsum(a1); o[2]=hsum(a2); o[3]=hsum(a3);
}

// Exchange 16 scalars with pair-partner lane; dst[0..15] gets the full packed
// 32-value vector in row order. Constant indices + SEL -> no local-mem spill.
__device__ __forceinline__ void exchange16(const float* myv, ull* dst, int rhalf){
#pragma unroll
  for (int i=0;i<8;i++){
    ull m = pack2(myv[2*i], myv[2*i+1]);
    ull o = __shfl_xor_sync(0xFFFFFFFFu, m, 1);
    dst[i]   = rhalf ? o : m;
    dst[8+i] = rhalf ? m : o;
  }
}

__global__ void __launch_bounds__(32)
rssm_kernel(const float* __restrict__ s0, const float* __restrict__ h0,
            const float* __restrict__ actions,
            const float* __restrict__ W_ih, const float* __restrict__ W_hh,
            const float* __restrict__ b_ih, const float* __restrict__ b_hh,
            const float* __restrict__ fc1_w, const float* __restrict__ fc1_b,
            const float* __restrict__ mean_w, const float* __restrict__ mean_b,
            const float* __restrict__ std_w, const float* __restrict__ std_b,
            float* __restrict__ out, int B, int T, int n_steps)
{
  __shared__ __align__(16) float sw[SMEM_FLOATS];
  const int tid = threadIdx.x;

  // ---- stage weights into the packed/skewed shared image ----
  for (int i=tid;i<SMEM_FLOATS;i+=32) sw[i]=0.0f;
  __syncthreads();
  for (int i=tid;i<32*32;i+=32){ int j=i>>5,k=i&31; sw[j*NH_STRIDE+((j>>4)<<2)+k]=W_hh[i]; }
  for (int i=tid;i<32*40;i+=32){ int j=i/40,k=i-j*40; sw[j*NH_STRIDE+((j>>4)<<2)+34+k]=W_ih[i]; }
  for (int i=tid;i<32*32;i+=32){
    int j=i>>5,k=i&31; int sk=((j>>4)<<2);
    sw[FC1_OFF + j*M_STRIDE+sk+k]=fc1_w[i];
    sw[MEAN_OFF+ j*M_STRIDE+sk+k]=mean_w[i];
    sw[STD_OFF + j*M_STRIDE+sk+k]=std_w[i];
  }
  {
    int j=tid; int sk=((j>>4)<<2);
    sw[j*NH_STRIDE+sk+32]          = b_ih[j]+b_hh[j];
    sw[FC1_OFF + j*M_STRIDE+sk+32] = fc1_b[j];
    sw[MEAN_OFF+ j*M_STRIDE+sk+32] = mean_b[j];
    sw[STD_OFF + j*M_STRIDE+sk+32] = std_b[j];
  }
  __syncthreads();

  const int rhalf = tid & 1;                       // which 16 output rows I own
  const int elem  = blockIdx.x*16 + (tid>>1);      // batch element

  const float* nhb = sw + (rhalf ? 16*NH_STRIDE+4 : 0);
  const float* f1b = sw + FC1_OFF  + (rhalf ? 16*M_STRIDE+4 : 0);
  const float* mnb = sw + MEAN_OFF + (rhalf ? 16*M_STRIDE+4 : 0);
  const float* sdb = sw + STD_OFF  + (rhalf ? 16*M_STRIDE+4 : 0);

  // v = [h(16 pairs), ONE, s(16 pairs), a(4 pairs), ZERO];  u = [hid(16), ONE, ZERO]
  ull v[38];
  ull u[18];
  {
    const float4* h4 = (const float4*)(h0 + (size_t)elem*32);
    const float4* s4 = (const float4*)(s0 + (size_t)elem*32);
#pragma unroll
    for (int q=0;q<8;q++){
      F4U th; th.f=h4[q]; v[2*q]=th.u.x;    v[2*q+1]=th.u.y;
      F4U ts; ts.f=s4[q]; v[17+2*q]=ts.u.x; v[18+2*q]=ts.u.y;
    }
    v[16]=pack2(1.0f,0.0f);
    v[37]=0ull;
    u[16]=pack2(1.0f,0.0f);
    u[17]=0ull;
    const float4* a4=(const float4*)(actions + (size_t)elem*T*8);
    F4U a0; a0.f=a4[0]; F4U a1; a1.f=a4[1];
    v[33]=a0.u.x; v[34]=a0.u.y; v[35]=a1.u.x; v[36]=a1.u.y;
  }

  for (int t=0;t<n_steps;t++){
    // prefetch next step's action (latency hidden behind this step's math)
    F4U an0, an1; an0.u.x=0ull; an0.u.y=0ull; an1.u.x=0ull; an1.u.y=0ull;
    if (t+1<n_steps){
      const float4* a4=(const float4*)(actions + ((size_t)elem*T + t+1)*8);
      an0.f=a4[0]; an1.f=a4[1];
    }

    // ---- h_t = tanh(W_ih @ [s,a] + b_ih + W_hh @ h + b_hh) ----
    float myh[16];
#pragma unroll
    for (int g=0;g<4;g++)
      dot4<19>(nhb+(g*4+0)*NH_STRIDE, nhb+(g*4+1)*NH_STRIDE,
               nhb+(g*4+2)*NH_STRIDE, nhb+(g*4+3)*NH_STRIDE, v, myh+g*4);
#pragma unroll
    for (int i=0;i<16;i++) myh[i]=tanh_fast(myh[i]);
    exchange16(myh, v, rhalf);                      // v[0..15] = new h

    // ---- hid = elu(fc1 @ h + b) ----
    float myhid[16];
#pragma unroll
    for (int g=0;g<4;g++)
      dot4<9>(f1b+(g*4+0)*M_STRIDE, f1b+(g*4+1)*M_STRIDE,
              f1b+(g*4+2)*M_STRIDE, f1b+(g*4+3)*M_STRIDE, v, myhid+g*4);
#pragma unroll
    for (int i=0;i<16;i++){ float x=myhid[i]; myhid[i]= x>0.0f ? x : (__expf(x)-1.0f); }
    exchange16(myhid, u, rhalf);                    // u[0..15] = hid

    // ---- mean = mean_w @ hid + b  (also next-step s) ----
    float mym[16];
#pragma unroll
    for (int g=0;g<4;g++)
      dot4<9>(mnb+(g*4+0)*M_STRIDE, mnb+(g*4+1)*M_STRIDE,
              mnb+(g*4+2)*M_STRIDE, mnb+(g*4+3)*M_STRIDE, u, mym+g*4);

    float* orow = out + ((size_t)t*B + elem)*64 + rhalf*16;
#pragma unroll
    for (int q=0;q<4;q++){
      float4 f; f.x=mym[4*q]; f.y=mym[4*q+1]; f.z=mym[4*q+2]; f.w=mym[4*q+3];
      ((float4*)orow)[q]=f;
    }
    exchange16(mym, v+17, rhalf);                   // v[17..32] = new s

    // ---- stddev = softplus(std_w @ hid + b) + 1e-5 ----
    float mys[16];
#pragma unroll
    for (int g=0;g<4;g++)
      dot4<9>(sdb+(g*4+0)*M_STRIDE, sdb+(g*4+1)*M_STRIDE,
              sdb+(g*4+2)*M_STRIDE, sdb+(g*4+3)*M_STRIDE, u, mys+g*4);
#pragma unroll
    for (int i=0;i<16;i++) mys[i]=softplus_fast(mys[i])+1e-5f;
#pragma unroll
    for (int q=0;q<4;q++){
      float4 f; f.x=mys[4*q]; f.y=mys[4*q+1]; f.z=mys[4*q+2]; f.w=mys[4*q+3];
      ((float4*)(orow+32))[q]=f;
    }

    // commit prefetched action into v
    v[33]=an0.u.x; v[34]=an0.u.y; v[35]=an1.u.x; v[36]=an1.u.y;
  }
}

extern "C" void kernel_launch(void* const* d_in, const int* in_sizes, int n_in,
                              void* d_out, int out_size) {
  const float* s0      = (const float*)d_in[0];
  const float* h0      = (const float*)d_in[1];
  const float* actions = (const float*)d_in[2];
  const float* W_ih    = (const float*)d_in[3];
  const float* W_hh    = (const float*)d_in[4];
  const float* b_ih    = (const float*)d_in[5];
  const float* b_hh    = (const float*)d_in[6];
  const float* fc1_w   = (const float*)d_in[7];
  const float* fc1_b   = (const float*)d_in[8];
  const float* mean_w  = (const float*)d_in[9];
  const float* mean_b  = (const float*)d_in[10];
  const float* std_w   = (const float*)d_in[11];
  const float* std_b   = (const float*)d_in[12];
  float* out = (float*)d_out;

  int B = in_sizes[0] / 32;                 // s0 is [B, 32]
  int T = in_sizes[2] / (B * 8);            // actions is [B, T, 8]
  int n_steps = out_size / (B * 64);        // out is [n_steps, B, 64]
  if (n_steps > T) n_steps = T;

  // hint: allow max shared carveout so up to 7 CTAs (23.6 KB each) co-reside
  cudaFuncSetAttribute(rssm_kernel, cudaFuncAttributePreferredSharedMemoryCarveout, 100);

  rssm_kernel<<<B/16, 32>>>(s0, h0, actions, W_ih, W_hh, b_ih, b_hh,
                            fc1_w, fc1_b, mean_w, mean_b, std_w, std_b,
                            out, B, T, n_steps);
}